// round 13
// baseline (speedup 1.0000x reference)
#include <cuda_runtime.h>
#include <cuda_bf16.h>
#include <cuda_fp16.h>
#include <cstdint>

#define NN 50000
#define NE 800000
#define NBATCH 8
#define HD 128
#define NBLK 391
#define NP (NBLK*128)   // 50048 padded rows
#define SCAN_NB 196

// ---------------- device scratch (static, no allocations) ----------------
// h and agg stored packed: one uint32 per channel = (hi fp16 << 16) | lo fp16,
// value = hi + lo (22-bit effective mantissa). Pad rows stay statically zero.
__device__ uint32_t g_hw[NP*HD];
__device__ uint32_t g_aggw[NP*HD];
__device__ __half g_Psrc[NP*HD];
__device__ float  g_Pdst[NP*HD];
__device__ int    g_cnt[NN];
__device__ int    g_fill[NN];
__device__ int    g_rowptr[NN+1];
__device__ int    g_bsum[SCAN_NB];
__device__ int    g_srcs[NE];
__device__ float4 g_ea[NE];
__device__ float  g_invdeg[NN];
__device__ float  g_w[NN];
__device__ float  g_gsum[NBATCH*HD];
__device__ float  g_gcnt[NBATCH];        // written ONCE by k_seginit; never zeroed after
__device__ float  g_bcsum[NBATCH*HD];
__device__ float  g_bccnt[NBATCH];
__device__ float  g_gbc[NBATCH*HD];      // b_upd + xBC @ Wu[384:512] (constant over repeats)
__device__ float  g_gb[NBATCH*HD];
__device__ float  g_S[HD];
__device__ float  g_sw;
// fp16 weights, [N][K] row-major (K contiguous)
__device__ __half g_B1h[256*128];
__device__ __half g_B2h[128*256];

// ---------------- smem geometry ----------------
#define PITCH 136                     // fp16 elements per row (272B, conflict-free)
#define TILE_ELEMS (128*PITCH)        // 17408 halfs per tile
#define SM_AHI 0
#define SM_ALO (TILE_ELEMS)
#define SM_B   (2*TILE_ELEMS)
#define SM_TOTAL_BYTES (3*TILE_ELEMS*2)   // 104448 -> 2 CTAs/SM

// ---------------- pack/unpack helpers ----------------
__device__ __forceinline__ uint32_t packf(float v){
    __half hi = __float2half_rn(v);
    __half lo = __float2half_rn(v - __half2float(hi));
    __half2 h2 = __halves2half2(lo, hi);    // .x = lo (low bits), .y = hi
    return *(uint32_t*)&h2;
}
__device__ __forceinline__ float unpackf(uint32_t w){
    __half2 h2 = *(__half2*)&w;
    return __half2float(h2.y) + __half2float(h2.x);
}

// ---------------- mma / ldmatrix helpers ----------------
__device__ __forceinline__ void mma16816(float* d, const uint32_t* a, const uint32_t* b){
    asm volatile("mma.sync.aligned.m16n8k16.row.col.f32.f16.f16.f32 "
        "{%0,%1,%2,%3}, {%4,%5,%6,%7}, {%8,%9}, {%0,%1,%2,%3};"
        : "+f"(d[0]), "+f"(d[1]), "+f"(d[2]), "+f"(d[3])
        : "r"(a[0]), "r"(a[1]), "r"(a[2]), "r"(a[3]), "r"(b[0]), "r"(b[1]));
}
__device__ __forceinline__ void ldsm4(uint32_t& r0, uint32_t& r1, uint32_t& r2, uint32_t& r3,
                                      uint32_t addr){
    asm volatile("ldmatrix.sync.aligned.m8n8.x4.shared.b16 {%0,%1,%2,%3}, [%4];"
        : "=r"(r0), "=r"(r1), "=r"(r2), "=r"(r3) : "r"(addr));
}

// load 128x128 packed-A block -> smem hi/lo fp16 tiles via byte_perm (no cvt)
__device__ __forceinline__ void load_A_packed(const uint32_t* A, __half* sAhi,
                                              __half* sAlo, int tid){
    const uint4* A4 = (const uint4*)A;
    #pragma unroll
    for (int i = 0; i < 16; i++){
        int f = tid + i*256;
        int r = f >> 5, c4 = f & 31;
        uint4 v = A4[f];
        uint32_t hi0 = __byte_perm(v.x, v.y, 0x7632);
        uint32_t lo0 = __byte_perm(v.x, v.y, 0x5410);
        uint32_t hi1 = __byte_perm(v.z, v.w, 0x7632);
        uint32_t lo1 = __byte_perm(v.z, v.w, 0x5410);
        *(uint2*)(sAhi + r*PITCH + c4*4) = make_uint2(hi0, hi1);
        *(uint2*)(sAlo + r*PITCH + c4*4) = make_uint2(lo0, lo1);
    }
}

// copy 128x128 fp16 block (row stride srcPitch) -> smem (pitch PITCH)
__device__ __forceinline__ void load_B_tile(const __half* src, int srcPitch,
                                            __half* dst, int tid){
    #pragma unroll
    for (int i = 0; i < 8; i++){
        int f = tid + i*256;
        int n = f >> 4, k8 = f & 15;
        *(uint4*)(dst + n*PITCH + k8*8) = *(const uint4*)(src + n*srcPitch + k8*8);
    }
}

// one K=128 compute stage: acc += Ahi*B (+ Alo*B when dual)
__device__ __forceinline__ void mma_stage(uint32_t sb, float acc[2][8][4], int w, int l,
                                          bool dual){
    const uint32_t AHI = SM_AHI*2, ALO = SM_ALO*2, BOF = SM_B*2;
    int wm = w >> 1, wn = w & 1;
    uint32_t acol = (l & 16) ? 16u : 0u;
    uint32_t aoff0 = (uint32_t)((wm*32 + (l & 15))*PITCH)*2 + acol;
    uint32_t aoff1 = aoff0 + 16*PITCH*2;
    uint32_t bcol = (l & 8) ? 16u : 0u;
    uint32_t boff = (uint32_t)((wn*64 + (l & 7) + ((l & 16) ? 8 : 0))*PITCH)*2 + bcol;
    #pragma unroll
    for (int ks = 0; ks < 8; ks++){
        uint32_t ko = (uint32_t)ks*32;
        uint32_t ah[2][4], al[2][4], bh[8][2];
        ldsm4(ah[0][0], ah[0][1], ah[0][2], ah[0][3], sb + AHI + aoff0 + ko);
        ldsm4(ah[1][0], ah[1][1], ah[1][2], ah[1][3], sb + AHI + aoff1 + ko);
        if (dual){
            ldsm4(al[0][0], al[0][1], al[0][2], al[0][3], sb + ALO + aoff0 + ko);
            ldsm4(al[1][0], al[1][1], al[1][2], al[1][3], sb + ALO + aoff1 + ko);
        }
        #pragma unroll
        for (int nb2 = 0; nb2 < 4; nb2++){
            uint32_t bo = boff + (uint32_t)(nb2*16*PITCH)*2 + ko;
            ldsm4(bh[2*nb2][0], bh[2*nb2][1], bh[2*nb2+1][0], bh[2*nb2+1][1], sb + BOF + bo);
        }
        #pragma unroll
        for (int mb = 0; mb < 2; mb++)
            #pragma unroll
            for (int nb = 0; nb < 8; nb++){
                mma16816(acc[mb][nb], ah[mb], bh[nb]);
                if (dual) mma16816(acc[mb][nb], al[mb], bh[nb]);
            }
    }
}

// ---------------- merged setup: zero state + pack both weight mats ----------
__global__ void k_setup(const float* __restrict__ Wm, const float* __restrict__ Wu){
    int i = blockIdx.x*blockDim.x + threadIdx.x;
    if (i < NN){ g_cnt[i] = 0; g_fill[i] = 0; }
    if (i < NBATCH*HD){ g_gsum[i] = 0.f; g_bcsum[i] = 0.f; }
    if (i < NBATCH){ g_gcnt[i] = 0.f; g_bccnt[i] = 0.f; }
    if (i < HD) g_S[i] = 0.f;
    if (i == 0) g_sw = 0.f;
    if (i < 256*128){
        int n = i >> 7, k = i & 127;
        float v = (n < 128) ? Wm[k*128 + n] : Wm[(128+k)*128 + (n-128)];
        g_B1h[i] = __float2half_rn(v);
        int n2 = i >> 8, k2 = i & 255;
        g_B2h[i] = __float2half_rn(Wu[k2*128 + n2]);
    }
}

// h0 = relu([x|x_mask] @ W_enc + b_enc), stored packed
__global__ void k_encode(const float* __restrict__ x, const float* __restrict__ xm,
                         const float* __restrict__ We, const float* __restrict__ be){
    int node = blockIdx.x*8 + (threadIdx.x >> 5);
    int c = threadIdx.x & 31;
    if (node >= NN) return;
    const float4* We4 = (const float4*)We;
    float4 acc = ((const float4*)be)[c];
    const float* xr = x  + node*5;
    const float* mr = xm + node*3;
    float in[8] = {xr[0], xr[1], xr[2], xr[3], xr[4], mr[0], mr[1], mr[2]};
    #pragma unroll
    for (int j = 0; j < 8; j++){
        float4 wv = We4[j*32 + c];
        acc.x += in[j]*wv.x; acc.y += in[j]*wv.y;
        acc.z += in[j]*wv.z; acc.w += in[j]*wv.w;
    }
    uint4 o;
    o.x = packf(fmaxf(acc.x, 0.f));
    o.y = packf(fmaxf(acc.y, 0.f));
    o.z = packf(fmaxf(acc.z, 0.f));
    o.w = packf(fmaxf(acc.w, 0.f));
    *(uint4*)&g_hw[(size_t)node*HD + c*4] = o;
}

__global__ void k_wcoef(const float* __restrict__ pos, const float* __restrict__ M,
                        const float* __restrict__ sp){
    int i = blockIdx.x*blockDim.x + threadIdx.x;
    if (i >= NN) return;
    float d0 = pos[i*2]   - sp[0];
    float d1 = pos[i*2+1] - sp[1];
    float sum = 0.f;
    #pragma unroll 8
    for (int j = 0; j < 64; j++)
        sum += __cosf(d0*M[j] + d1*M[64+j]);
    g_w[i] = sum * (1.f/64.f);
}

__global__ void k_count(const int* __restrict__ ei){
    int e = blockIdx.x*blockDim.x + threadIdx.x;
    if (e < NE) atomicAdd(&g_cnt[ei[NE + e]], 1);
}

// ---- 3-phase parallel scan of degree counts -> rowptr ----
__global__ void k_scan1(){
    int b = blockIdx.x, t = threadIdx.x;
    int n = b*256 + t;
    int v = (n < NN) ? g_cnt[n] : 0;
    if (n < NN) g_invdeg[n] = 1.f / (float)max(v, 1);
    int lane = t & 31, wp = t >> 5;
    int x = v;
    #pragma unroll
    for (int off = 1; off < 32; off <<= 1){
        int y = __shfl_up_sync(0xffffffffu, x, off);
        if (lane >= off) x += y;
    }
    __shared__ int ws[8];
    if (lane == 31) ws[wp] = x;
    __syncthreads();
    if (t == 0){
        int run = 0;
        #pragma unroll
        for (int i = 0; i < 8; i++){ int tmp = ws[i]; ws[i] = run; run += tmp; }
        g_bsum[b] = run;
    }
    __syncthreads();
    if (n < NN) g_rowptr[n] = x - v + ws[wp];
}

__global__ void k_scan2(){
    int t = threadIdx.x;
    int v = (t < SCAN_NB) ? g_bsum[t] : 0;
    int lane = t & 31, wp = t >> 5;
    int x = v;
    #pragma unroll
    for (int off = 1; off < 32; off <<= 1){
        int y = __shfl_up_sync(0xffffffffu, x, off);
        if (lane >= off) x += y;
    }
    __shared__ int ws[8];
    if (lane == 31) ws[wp] = x;
    __syncthreads();
    if (t == 0){
        int run = 0;
        #pragma unroll
        for (int i = 0; i < 8; i++){ int tmp = ws[i]; ws[i] = run; run += tmp; }
        g_rowptr[NN] = run;
    }
    __syncthreads();
    if (t < SCAN_NB) g_bsum[t] = x - v + ws[wp];
}

__global__ void k_scan3(){
    int n = blockIdx.x*256 + threadIdx.x;
    if (n < NN) g_rowptr[n] += g_bsum[n >> 8];
}

__global__ void k_scatter(const int* __restrict__ ei, const float* __restrict__ ea){
    int e = blockIdx.x*blockDim.x + threadIdx.x;
    if (e >= NE) return;
    int s = ei[e];
    int d = ei[NE + e];
    int p = g_rowptr[d] + atomicAdd(&g_fill[d], 1);
    g_srcs[p] = s;
    const float* a = ea + e*3;
    g_ea[p] = make_float4(a[0], a[1], a[2], 0.f);
}

// initial segment sums; the ONLY writer of g_gcnt / g_bccnt (constant after)
__global__ void k_seginit(const int* __restrict__ batch, const float* __restrict__ xm){
    const int nchunk = (NN + gridDim.x - 1) / gridDim.x;
    int n0 = blockIdx.x * nchunk;
    int n1 = min(n0 + nchunk, NN);
    int t = threadIdx.x;
    if (n0 >= n1) return;
    int cur = batch[n0];
    float aG = 0.f, aB = 0.f, cG = 0.f, cB = 0.f;
    for (int n = n0; n < n1; n++){
        int b = batch[n];
        if (b != cur){
            atomicAdd(&g_gsum[cur*HD+t], aG);
            atomicAdd(&g_bcsum[cur*HD+t], aB);
            if (t == 0){ atomicAdd(&g_gcnt[cur], cG); atomicAdd(&g_bccnt[cur], cB); }
            aG = aB = cG = cB = 0.f; cur = b;
        }
        float hv = unpackf(g_hw[n*HD + t]);
        float bc = xm[n*3 + 2];
        aG += hv; aB += hv*bc;
        if (t == 0){ cG += 1.f; cB += bc; }
    }
    atomicAdd(&g_gsum[cur*HD+t], aG);
    atomicAdd(&g_bcsum[cur*HD+t], aB);
    if (t == 0){ atomicAdd(&g_gcnt[cur], cG); atomicAdd(&g_bccnt[cur], cB); }
}

// gbc = b_upd + xBC @ Wu[384:512]   (constant over repeats)
__global__ void k_initgbc(const float* __restrict__ Wu, const float* __restrict__ bu){
    int g = blockIdx.x, t = threadIdx.x;
    __shared__ float sx[128];
    float bcc = fmaxf(g_bccnt[g], 1.f);
    sx[t] = g_bcsum[g*HD + t] / bcc;
    __syncthreads();
    float acc = bu[t];
    #pragma unroll 4
    for (int k = 0; k < 128; k++) acc += sx[k] * Wu[(384+k)*128 + t];
    g_gbc[g*HD + t] = acc;
}

// gb = gbc + xg @ Wu[256:384]; finishes seg-mean; re-zeros SUMS only.
__global__ void k_prep(const float* __restrict__ Wu){
    int g = blockIdx.x, t = threadIdx.x;
    __shared__ float sx[128];
    float c = fmaxf(g_gcnt[g], 1.f);
    sx[t] = g_gsum[g*HD + t] / c;
    __syncthreads();
    float acc = g_gbc[g*HD + t];
    #pragma unroll 4
    for (int k = 0; k < 128; k++) acc += sx[k] * Wu[(256+k)*128 + t];
    g_gb[g*HD + t] = acc;
    g_gsum[g*HD + t] = 0.f;
}

// seg sums only (counts are constant, owned by k_seginit)
__global__ void k_segsum(const int* __restrict__ batch){
    const int nchunk = (NN + gridDim.x - 1) / gridDim.x;
    int n0 = blockIdx.x * nchunk;
    int n1 = min(n0 + nchunk, NN);
    int t = threadIdx.x;
    if (n0 >= n1) return;
    int cur = batch[n0];
    float aG = 0.f;
    for (int n = n0; n < n1; n++){
        int b = batch[n];
        if (b != cur){
            atomicAdd(&g_gsum[cur*HD+t], aG);
            aG = 0.f; cur = b;
        }
        aG += unpackf(g_hw[n*HD + t]);
    }
    atomicAdd(&g_gsum[cur*HD+t], aG);
}

// ---- GEMM1: Psrc(fp16, 1-pass)/Pdst(fp32, 2-pass) = h @ B1^T -----------------
__global__ void __launch_bounds__(256, 2) k_gemm1(const float* __restrict__ bm){
    extern __shared__ __half sm[];
    uint32_t sb = (uint32_t)__cvta_generic_to_shared(sm);
    int tid = threadIdx.x;
    int w = tid >> 5, l = tid & 31;
    int row0 = blockIdx.x * 128;
    int cchunk = blockIdx.y;          // 0 -> Psrc (fp16, single pass), 1 -> Pdst

    load_A_packed(g_hw + (size_t)row0*128, sm + SM_AHI, sm + SM_ALO, tid);
    load_B_tile(g_B1h + (size_t)cchunk*128*128, 128, sm + SM_B, tid);
    __syncthreads();

    float acc[2][8][4];
    #pragma unroll
    for (int mb = 0; mb < 2; mb++)
        #pragma unroll
        for (int nb = 0; nb < 8; nb++)
            #pragma unroll
            for (int c = 0; c < 4; c++) acc[mb][nb][c] = 0.f;

    if (cchunk == 0) mma_stage(sb, acc, w, l, false);
    else             mma_stage(sb, acc, w, l, true);

    int wm = w >> 1, wn = w & 1;
    int g = l >> 2, t2 = (l & 3) * 2;
    if (cchunk == 0){
        #pragma unroll
        for (int mb = 0; mb < 2; mb++){
            int row = row0 + wm*32 + mb*16 + g;
            #pragma unroll
            for (int nb = 0; nb < 8; nb++){
                int col = wn*64 + nb*8 + t2;
                *(__half2*)&g_Psrc[(size_t)row*128 + col] =
                    __floats2half2_rn(acc[mb][nb][0], acc[mb][nb][1]);
                *(__half2*)&g_Psrc[(size_t)(row+8)*128 + col] =
                    __floats2half2_rn(acc[mb][nb][2], acc[mb][nb][3]);
            }
        }
    } else {
        #pragma unroll
        for (int mb = 0; mb < 2; mb++){
            int row = row0 + wm*32 + mb*16 + g;
            #pragma unroll
            for (int nb = 0; nb < 8; nb++){
                int col = wn*64 + nb*8 + t2;
                float bias0 = bm[col], bias1 = bm[col+1];
                *(float2*)&g_Pdst[(size_t)row*128 + col] =
                    make_float2(acc[mb][nb][0] + bias0, acc[mb][nb][1] + bias1);
                *(float2*)&g_Pdst[(size_t)(row+8)*128 + col] =
                    make_float2(acc[mb][nb][2] + bias0, acc[mb][nb][3] + bias1);
            }
        }
    }
}

// ------- edge aggregation over CSR: one warp per node, 4 channels/lane --------
__global__ void k_agg(const float* __restrict__ Wm){
    int n = blockIdx.x*8 + (threadIdx.x >> 5);
    if (n >= NN) return;
    int l = threadIdx.x & 31;
    int c = l*4;
    float4 base = *(const float4*)&g_Pdst[(size_t)n*128 + c];   // includes b_msg
    float4 w0 = *(const float4*)&Wm[256*128 + c];
    float4 w1 = *(const float4*)&Wm[257*128 + c];
    float4 w2 = *(const float4*)&Wm[258*128 + c];
    int s0 = g_rowptr[n], s1 = g_rowptr[n+1];
    float a0 = 0.f, a1 = 0.f, a2 = 0.f, a3 = 0.f;
    int k = s0;
    for (; k + 1 < s1; k += 2){
        int sA = g_srcs[k], sB = g_srcs[k+1];
        float4 eA = g_ea[k], eB = g_ea[k+1];
        uint2 pA = *(const uint2*)&g_Psrc[(size_t)sA*128 + c];
        uint2 pB = *(const uint2*)&g_Psrc[(size_t)sB*128 + c];
        float2 pA01 = __half22float2(*(__half2*)&pA.x);
        float2 pA23 = __half22float2(*(__half2*)&pA.y);
        float2 pB01 = __half22float2(*(__half2*)&pB.x);
        float2 pB23 = __half22float2(*(__half2*)&pB.y);
        float tA0 = base.x + eA.x*w0.x + eA.y*w1.x + eA.z*w2.x;
        float tA1 = base.y + eA.x*w0.y + eA.y*w1.y + eA.z*w2.y;
        float tA2 = base.z + eA.x*w0.z + eA.y*w1.z + eA.z*w2.z;
        float tA3 = base.w + eA.x*w0.w + eA.y*w1.w + eA.z*w2.w;
        float tB0 = base.x + eB.x*w0.x + eB.y*w1.x + eB.z*w2.x;
        float tB1 = base.y + eB.x*w0.y + eB.y*w1.y + eB.z*w2.y;
        float tB2 = base.z + eB.x*w0.z + eB.y*w1.z + eB.z*w2.z;
        float tB3 = base.w + eB.x*w0.w + eB.y*w1.w + eB.z*w2.w;
        a0 += fmaxf(pA01.x + tA0, 0.f) + fmaxf(pB01.x + tB0, 0.f);
        a1 += fmaxf(pA01.y + tA1, 0.f) + fmaxf(pB01.y + tB1, 0.f);
        a2 += fmaxf(pA23.x + tA2, 0.f) + fmaxf(pB23.x + tB2, 0.f);
        a3 += fmaxf(pA23.y + tA3, 0.f) + fmaxf(pB23.y + tB3, 0.f);
    }
    if (k < s1){
        int s = g_srcs[k];
        float4 e = g_ea[k];
        uint2 p = *(const uint2*)&g_Psrc[(size_t)s*128 + c];
        float2 p01 = __half22float2(*(__half2*)&p.x);
        float2 p23 = __half22float2(*(__half2*)&p.y);
        a0 += fmaxf(p01.x + base.x + e.x*w0.x + e.y*w1.x + e.z*w2.x, 0.f);
        a1 += fmaxf(p01.y + base.y + e.x*w0.y + e.y*w1.y + e.z*w2.y, 0.f);
        a2 += fmaxf(p23.x + base.z + e.x*w0.z + e.y*w1.z + e.z*w2.z, 0.f);
        a3 += fmaxf(p23.y + base.w + e.x*w0.w + e.y*w1.w + e.z*w2.w, 0.f);
    }
    float inv = g_invdeg[n];
    uint4 o;
    o.x = packf(a0*inv); o.y = packf(a1*inv);
    o.z = packf(a2*inv); o.w = packf(a3*inv);
    *(uint4*)&g_aggw[(size_t)n*HD + c] = o;
}

// ---------------- GEMM2: h += relu([h|agg] @ B2^T + gb[batch]) ----------------
__global__ void __launch_bounds__(256, 2) k_gemm2(const int* __restrict__ batch){
    extern __shared__ __half sm[];
    uint32_t sb = (uint32_t)__cvta_generic_to_shared(sm);
    int tid = threadIdx.x;
    int w = tid >> 5, l = tid & 31;
    int row0 = blockIdx.x * 128;

    float acc[2][8][4];
    #pragma unroll
    for (int mb = 0; mb < 2; mb++)
        #pragma unroll
        for (int nb = 0; nb < 8; nb++)
            #pragma unroll
            for (int c = 0; c < 4; c++) acc[mb][nb][c] = 0.f;

    for (int kh = 0; kh < 2; kh++){
        if (kh) __syncthreads();
        const uint32_t* A = (kh == 0 ? g_hw : g_aggw) + (size_t)row0*128;
        load_A_packed(A, sm + SM_AHI, sm + SM_ALO, tid);
        load_B_tile(g_B2h + kh*128, 256, sm + SM_B, tid);
        __syncthreads();
        mma_stage(sb, acc, w, l, true);
    }

    int wm = w >> 1, wn = w & 1;
    int g = l >> 2, t2 = (l & 3) * 2;
    #pragma unroll
    for (int mb = 0; mb < 2; mb++){
        int row_a = row0 + wm*32 + mb*16 + g;
        #pragma unroll
        for (int half = 0; half < 2; half++){
            int row = row_a + half*8;
            if (row < NN){
                int b = batch[row];
                #pragma unroll
                for (int nb = 0; nb < 8; nb++){
                    int col = wn*64 + nb*8 + t2;
                    float v0 = acc[mb][nb][half*2+0] + g_gb[b*128 + col];
                    float v1 = acc[mb][nb][half*2+1] + g_gb[b*128 + col + 1];
                    uint32_t* hp = g_hw + (size_t)row*128 + col;
                    float h0 = unpackf(hp[0]) + fmaxf(v0, 0.f);
                    float h1 = unpackf(hp[1]) + fmaxf(v1, 0.f);
                    hp[0] = packf(h0);
                    hp[1] = packf(h1);
                }
            } else {
                #pragma unroll
                for (int nb = 0; nb < 8; nb++){
                    int col = wn*64 + nb*8 + t2;
                    *(uint2*)&g_hw[(size_t)row*128 + col] = make_uint2(0u, 0u);
                }
            }
        }
    }
}

// ---------------- decode + weighted global sums (warp per 32 nodes) ----------
__global__ void k_decode(const float* __restrict__ Wd, const float* __restrict__ bd,
                         float* __restrict__ out){
    int gw = (blockIdx.x*blockDim.x + threadIdx.x) >> 5;
    int l = threadIdx.x & 31;
    int n0 = gw * 32;
    if (n0 >= NN) return;
    int n1 = min(n0 + 32, NN);
    float wd0[4], wd1[4], wd2[4], wd3[4];
    #pragma unroll
    for (int c = 0; c < 4; c++){
        wd0[c] = Wd[(l*4+0)*4 + c];
        wd1[c] = Wd[(l*4+1)*4 + c];
        wd2[c] = Wd[(l*4+2)*4 + c];
        wd3[c] = Wd[(l*4+3)*4 + c];
    }
    float b0 = bd[0], b1 = bd[1], b2 = bd[2], b3 = bd[3];
    float S0=0.f, S1=0.f, S2=0.f, S3=0.f, wacc=0.f;
    for (int n = n0; n < n1; n++){
        uint4 hw = *(const uint4*)&g_hw[(size_t)n*128 + l*4];
        float h0 = unpackf(hw.x), h1 = unpackf(hw.y);
        float h2 = unpackf(hw.z), h3 = unpackf(hw.w);
        float wn = g_w[n];
        float onew = 1.f + wn;
        S0 += onew*h0; S1 += onew*h1; S2 += onew*h2; S3 += onew*h3;
        if (l == 0) wacc += wn;
        float p0 = h0*wd0[0] + h1*wd1[0] + h2*wd2[0] + h3*wd3[0];
        float p1 = h0*wd0[1] + h1*wd1[1] + h2*wd2[1] + h3*wd3[1];
        float p2 = h0*wd0[2] + h1*wd1[2] + h2*wd2[2] + h3*wd3[2];
        float p3 = h0*wd0[3] + h1*wd1[3] + h2*wd2[3] + h3*wd3[3];
        #pragma unroll
        for (int off = 16; off > 0; off >>= 1){
            p0 += __shfl_down_sync(0xffffffffu, p0, off);
            p1 += __shfl_down_sync(0xffffffffu, p1, off);
            p2 += __shfl_down_sync(0xffffffffu, p2, off);
            p3 += __shfl_down_sync(0xffffffffu, p3, off);
        }
        if (l == 0)
            *(float4*)&out[(size_t)(1+n)*4] = make_float4(p0+b0, p1+b1, p2+b2, p3+b3);
    }
    atomicAdd(&g_S[l*4+0], S0);
    atomicAdd(&g_S[l*4+1], S1);
    atomicAdd(&g_S[l*4+2], S2);
    atomicAdd(&g_S[l*4+3], S3);
    if (l == 0) atomicAdd(&g_sw, wacc);
}

__global__ void k_final(const float* __restrict__ Wd, const float* __restrict__ bd,
                        float* __restrict__ out){
    __shared__ float sred[4][4];
    int t = threadIdx.x;
    int lane = t & 31, wp = t >> 5;
    float enc = g_S[t] / ((float)NN + g_sw);
    float p0 = enc*Wd[t*4], p1 = enc*Wd[t*4+1], p2 = enc*Wd[t*4+2], p3 = enc*Wd[t*4+3];
    #pragma unroll
    for (int off = 16; off > 0; off >>= 1){
        p0 += __shfl_down_sync(0xffffffffu, p0, off);
        p1 += __shfl_down_sync(0xffffffffu, p1, off);
        p2 += __shfl_down_sync(0xffffffffu, p2, off);
        p3 += __shfl_down_sync(0xffffffffu, p3, off);
    }
    if (lane == 0){ sred[wp][0]=p0; sred[wp][1]=p1; sred[wp][2]=p2; sred[wp][3]=p3; }
    __syncthreads();
    if (t < 4)
        out[t] = sred[0][t] + sred[1][t] + sred[2][t] + sred[3][t] + bd[t];
}

// ---------------- launch ----------------
extern "C" void kernel_launch(void* const* d_in, const int* in_sizes, int n_in,
                              void* d_out, int out_size){
    (void)in_sizes; (void)n_in; (void)out_size;
    const float* x   = (const float*)d_in[0];
    const float* xm  = (const float*)d_in[1];
    const int*   ei  = (const int*)  d_in[2];
    const float* ea  = (const float*)d_in[3];
    const float* pos = (const float*)d_in[4];
    const int*   bat = (const int*)  d_in[5];
    const float* sp  = (const float*)d_in[6];
    const float* M   = (const float*)d_in[7];
    const float* We  = (const float*)d_in[8];
    const float* be  = (const float*)d_in[9];
    const float* Wm  = (const float*)d_in[10];
    const float* bm  = (const float*)d_in[11];
    const float* Wu  = (const float*)d_in[12];
    const float* bu  = (const float*)d_in[13];
    const float* Wd  = (const float*)d_in[14];
    const float* bd  = (const float*)d_in[15];
    float* out = (float*)d_out;

    static int attr_done = 0;
    if (!attr_done){
        cudaFuncSetAttribute(k_gemm1, cudaFuncAttributeMaxDynamicSharedMemorySize, SM_TOTAL_BYTES);
        cudaFuncSetAttribute(k_gemm2, cudaFuncAttributeMaxDynamicSharedMemorySize, SM_TOTAL_BYTES);
        attr_done = 1;
    }

    dim3 g1(NBLK, 2);

    k_setup  <<<(NN+255)/256, 256>>>(Wm, Wu);
    k_encode <<<(NN+7)/8, 256>>>(x, xm, We, be);
    k_wcoef  <<<(NN+255)/256, 256>>>(pos, M, sp);
    k_count  <<<(NE+255)/256, 256>>>(ei);
    k_scan1  <<<SCAN_NB, 256>>>();
    k_gemm1  <<<g1, 256, SM_TOTAL_BYTES>>>(bm);   // repeat 0 GEMM1 (hoisted)
    k_scan2  <<<1, 256>>>();
    k_scan3  <<<SCAN_NB, 256>>>();
    k_scatter<<<(NE+255)/256, 256>>>(ei, ea);
    k_seginit<<<784, 128>>>(bat, xm);
    k_initgbc<<<NBATCH, 128>>>(Wu, bu);
    k_prep   <<<NBATCH, 128>>>(Wu);

    for (int r = 0; r < 4; r++){
        if (r > 0) k_gemm1<<<g1, 256, SM_TOTAL_BYTES>>>(bm);
        k_agg  <<<(NN+7)/8, 256>>>(Wm);
        k_gemm2<<<NBLK, 256, SM_TOTAL_BYTES>>>(bat);
        if (r < 3){
            k_segsum<<<784, 128>>>(bat);
            k_prep  <<<NBATCH, 128>>>(Wu);
        }
    }

    k_decode<<<196, 256>>>(Wd, bd, out);
    k_final <<<1, 128>>>(Wd, bd, out);
}

// round 15
// speedup vs baseline: 1.0497x; 1.0497x over previous
#include <cuda_runtime.h>
#include <cuda_bf16.h>
#include <cuda_fp16.h>
#include <cstdint>

#define NN 50000
#define NE 800000
#define NBATCH 8
#define HD 128
#define NBLK 391
#define NP (NBLK*128)   // 50048 padded rows
#define SCAN_NB 196

// ---------------- device scratch (static, no allocations) ----------------
__device__ float  g_h[NP*HD];
__device__ __half g_Psrc[NP*HD];
__device__ float  g_Pdst[NP*HD];
__device__ float  g_agg[NP*HD];
__device__ int    g_cnt[NN];
__device__ int    g_fill[NN];
__device__ int    g_rowptr[NN+1];
__device__ int    g_bsum[SCAN_NB];
__device__ int    g_srcs[NE];
__device__ float4 g_ea[NE];
__device__ float  g_invdeg[NN];
__device__ float  g_w[NN];
__device__ float  g_gsum[NBATCH*HD];
__device__ float  g_gcnt[NBATCH];        // written ONCE by k_seginit; never zeroed after
__device__ float  g_bcsum[NBATCH*HD];
__device__ float  g_bccnt[NBATCH];
__device__ float  g_gbc[NBATCH*HD];      // b_upd + xBC @ Wu[384:512] (constant over repeats)
__device__ float  g_gb[NBATCH*HD];
__device__ float  g_S[HD];
__device__ float  g_sw;
// fp16 weights, [N][K] row-major (K contiguous)
__device__ __half g_B1h[256*128];
__device__ __half g_B2h[128*256];

// ---------------- smem geometry ----------------
#define PITCH 136                     // fp16 elements per row (272B, conflict-free)
#define TILE_ELEMS (128*PITCH)        // 17408 halfs per tile
// gemm2: AHI | ALO | B  (3 tiles, 2 CTAs/SM)
#define SM_AHI 0
#define SM_ALO (TILE_ELEMS)
#define SM_B2  (2*TILE_ELEMS)
#define SM2_TOTAL_BYTES (3*TILE_ELEMS*2)   // 104448
// gemm1: AHI | B        (2 tiles, 3 CTAs/SM)
#define SM_B1  (TILE_ELEMS)
#define SM1_TOTAL_BYTES (2*TILE_ELEMS*2)   // 69632

// ---------------- mma / ldmatrix helpers ----------------
__device__ __forceinline__ void mma16816(float* d, const uint32_t* a, const uint32_t* b){
    asm volatile("mma.sync.aligned.m16n8k16.row.col.f32.f16.f16.f32 "
        "{%0,%1,%2,%3}, {%4,%5,%6,%7}, {%8,%9}, {%0,%1,%2,%3};"
        : "+f"(d[0]), "+f"(d[1]), "+f"(d[2]), "+f"(d[3])
        : "r"(a[0]), "r"(a[1]), "r"(a[2]), "r"(a[3]), "r"(b[0]), "r"(b[1]));
}
__device__ __forceinline__ void ldsm4(uint32_t& r0, uint32_t& r1, uint32_t& r2, uint32_t& r3,
                                      uint32_t addr){
    asm volatile("ldmatrix.sync.aligned.m8n8.x4.shared.b16 {%0,%1,%2,%3}, [%4];"
        : "=r"(r0), "=r"(r1), "=r"(r2), "=r"(r3) : "r"(addr));
}
// pack two floats (lo elem, hi elem) as fp16x2 word (memory order lo,hi)
__device__ __forceinline__ uint32_t hf2(float lo, float hi){
    uint32_t r; asm("cvt.rn.f16x2.f32 %0, %1, %2;" : "=r"(r) : "f"(hi), "f"(lo));
    return r;
}

// load 128x128 float A block -> smem hi/lo fp16 tiles (pitch PITCH)
__device__ __forceinline__ void load_A_tile(const float* A, __half* sAhi,
                                            __half* sAlo, int tid){
    const float4* A4 = (const float4*)A;
    #pragma unroll
    for (int i = 0; i < 16; i++){
        int f = tid + i*256;
        int r = f >> 5, c4 = f & 31;
        float4 v = A4[f];
        float h0 = __half2float(__float2half_rn(v.x));
        float h1 = __half2float(__float2half_rn(v.y));
        float h2 = __half2float(__float2half_rn(v.z));
        float h3 = __half2float(__float2half_rn(v.w));
        uint2 hp = make_uint2(hf2(h0, h1), hf2(h2, h3));
        uint2 lp = make_uint2(hf2(v.x - h0, v.y - h1), hf2(v.z - h2, v.w - h3));
        *(uint2*)(sAhi + r*PITCH + c4*4) = hp;
        *(uint2*)(sAlo + r*PITCH + c4*4) = lp;
    }
}

// load 128x128 float A block -> smem hi-only fp16 tile
__device__ __forceinline__ void load_A_hi(const float* A, __half* sAhi, int tid){
    const float4* A4 = (const float4*)A;
    #pragma unroll
    for (int i = 0; i < 16; i++){
        int f = tid + i*256;
        int r = f >> 5, c4 = f & 31;
        float4 v = A4[f];
        uint2 hp = make_uint2(hf2(v.x, v.y), hf2(v.z, v.w));
        *(uint2*)(sAhi + r*PITCH + c4*4) = hp;
    }
}

// copy 128x128 fp16 block (row stride srcPitch) -> smem (pitch PITCH)
__device__ __forceinline__ void load_B_tile(const __half* src, int srcPitch,
                                            __half* dst, int tid){
    #pragma unroll
    for (int i = 0; i < 8; i++){
        int f = tid + i*256;
        int n = f >> 4, k8 = f & 15;
        *(uint4*)(dst + n*PITCH + k8*8) = *(const uint4*)(src + n*srcPitch + k8*8);
    }
}

// single-pass K=128 stage (gemm1 layout: B at SM_B1): acc += Ahi*B
__device__ __forceinline__ void mma_stage1(uint32_t sb, float acc[2][8][4], int w, int l){
    const uint32_t BOF = SM_B1*2;
    int wm = w >> 1, wn = w & 1;
    uint32_t acol = (l & 16) ? 16u : 0u;
    uint32_t aoff0 = (uint32_t)((wm*32 + (l & 15))*PITCH)*2 + acol;
    uint32_t aoff1 = aoff0 + 16*PITCH*2;
    uint32_t bcol = (l & 8) ? 16u : 0u;
    uint32_t boff = (uint32_t)((wn*64 + (l & 7) + ((l & 16) ? 8 : 0))*PITCH)*2 + bcol;
    #pragma unroll
    for (int ks = 0; ks < 8; ks++){
        uint32_t ko = (uint32_t)ks*32;
        uint32_t ah[2][4], bh[8][2];
        ldsm4(ah[0][0], ah[0][1], ah[0][2], ah[0][3], sb + aoff0 + ko);
        ldsm4(ah[1][0], ah[1][1], ah[1][2], ah[1][3], sb + aoff1 + ko);
        #pragma unroll
        for (int nb2 = 0; nb2 < 4; nb2++){
            uint32_t bo = boff + (uint32_t)(nb2*16*PITCH)*2 + ko;
            ldsm4(bh[2*nb2][0], bh[2*nb2][1], bh[2*nb2+1][0], bh[2*nb2+1][1], sb + BOF + bo);
        }
        #pragma unroll
        for (int mb = 0; mb < 2; mb++)
            #pragma unroll
            for (int nb = 0; nb < 8; nb++)
                mma16816(acc[mb][nb], ah[mb], bh[nb]);
    }
}

// dual-pass K=128 stage (gemm2 layout: ALO at SM_ALO, B at SM_B2)
__device__ __forceinline__ void mma_stage2(uint32_t sb, float acc[2][8][4], int w, int l){
    const uint32_t ALO = SM_ALO*2, BOF = SM_B2*2;
    int wm = w >> 1, wn = w & 1;
    uint32_t acol = (l & 16) ? 16u : 0u;
    uint32_t aoff0 = (uint32_t)((wm*32 + (l & 15))*PITCH)*2 + acol;
    uint32_t aoff1 = aoff0 + 16*PITCH*2;
    uint32_t bcol = (l & 8) ? 16u : 0u;
    uint32_t boff = (uint32_t)((wn*64 + (l & 7) + ((l & 16) ? 8 : 0))*PITCH)*2 + bcol;
    #pragma unroll
    for (int ks = 0; ks < 8; ks++){
        uint32_t ko = (uint32_t)ks*32;
        uint32_t ah[2][4], al[2][4], bh[8][2];
        ldsm4(ah[0][0], ah[0][1], ah[0][2], ah[0][3], sb + aoff0 + ko);
        ldsm4(ah[1][0], ah[1][1], ah[1][2], ah[1][3], sb + aoff1 + ko);
        ldsm4(al[0][0], al[0][1], al[0][2], al[0][3], sb + ALO + aoff0 + ko);
        ldsm4(al[1][0], al[1][1], al[1][2], al[1][3], sb + ALO + aoff1 + ko);
        #pragma unroll
        for (int nb2 = 0; nb2 < 4; nb2++){
            uint32_t bo = boff + (uint32_t)(nb2*16*PITCH)*2 + ko;
            ldsm4(bh[2*nb2][0], bh[2*nb2][1], bh[2*nb2+1][0], bh[2*nb2+1][1], sb + BOF + bo);
        }
        #pragma unroll
        for (int mb = 0; mb < 2; mb++)
            #pragma unroll
            for (int nb = 0; nb < 8; nb++){
                mma16816(acc[mb][nb], ah[mb], bh[nb]);
                mma16816(acc[mb][nb], al[mb], bh[nb]);
            }
    }
}

// ---------------- merged setup: zero state + pack both weight mats ----------
__global__ void k_setup(const float* __restrict__ Wm, const float* __restrict__ Wu){
    int i = blockIdx.x*blockDim.x + threadIdx.x;
    if (i < NN){ g_cnt[i] = 0; g_fill[i] = 0; }
    if (i < NBATCH*HD){ g_gsum[i] = 0.f; g_bcsum[i] = 0.f; }
    if (i < NBATCH){ g_gcnt[i] = 0.f; g_bccnt[i] = 0.f; }
    if (i < HD) g_S[i] = 0.f;
    if (i == 0) g_sw = 0.f;
    if (i < 256*128){
        int n = i >> 7, k = i & 127;
        float v = (n < 128) ? Wm[k*128 + n] : Wm[(128+k)*128 + (n-128)];
        g_B1h[i] = __float2half_rn(v);
        int n2 = i >> 8, k2 = i & 255;
        g_B2h[i] = __float2half_rn(Wu[k2*128 + n2]);
    }
}

// h0 = relu([x|x_mask] @ W_enc + b_enc)  — 32 threads per node, float4 cols
__global__ void k_encode(const float* __restrict__ x, const float* __restrict__ xm,
                         const float* __restrict__ We, const float* __restrict__ be){
    int node = blockIdx.x*8 + (threadIdx.x >> 5);
    int c = threadIdx.x & 31;
    if (node >= NN) return;
    const float4* We4 = (const float4*)We;
    float4 acc = ((const float4*)be)[c];
    const float* xr = x  + node*5;
    const float* mr = xm + node*3;
    float in[8] = {xr[0], xr[1], xr[2], xr[3], xr[4], mr[0], mr[1], mr[2]};
    #pragma unroll
    for (int j = 0; j < 8; j++){
        float4 wv = We4[j*32 + c];
        acc.x += in[j]*wv.x; acc.y += in[j]*wv.y;
        acc.z += in[j]*wv.z; acc.w += in[j]*wv.w;
    }
    acc.x = fmaxf(acc.x, 0.f); acc.y = fmaxf(acc.y, 0.f);
    acc.z = fmaxf(acc.z, 0.f); acc.w = fmaxf(acc.w, 0.f);
    *(float4*)&g_h[(size_t)node*HD + c*4] = acc;
}

__global__ void k_wcoef(const float* __restrict__ pos, const float* __restrict__ M,
                        const float* __restrict__ sp){
    int i = blockIdx.x*blockDim.x + threadIdx.x;
    if (i >= NN) return;
    float d0 = pos[i*2]   - sp[0];
    float d1 = pos[i*2+1] - sp[1];
    float sum = 0.f;
    #pragma unroll 8
    for (int j = 0; j < 64; j++)
        sum += __cosf(d0*M[j] + d1*M[64+j]);
    g_w[i] = sum * (1.f/64.f);
}

__global__ void k_count(const int* __restrict__ ei){
    int e = blockIdx.x*blockDim.x + threadIdx.x;
    if (e < NE) atomicAdd(&g_cnt[ei[NE + e]], 1);
}

// ---- 3-phase parallel scan of degree counts -> rowptr ----
__global__ void k_scan1(){
    int b = blockIdx.x, t = threadIdx.x;
    int n = b*256 + t;
    int v = (n < NN) ? g_cnt[n] : 0;
    if (n < NN) g_invdeg[n] = 1.f / (float)max(v, 1);
    int lane = t & 31, wp = t >> 5;
    int x = v;
    #pragma unroll
    for (int off = 1; off < 32; off <<= 1){
        int y = __shfl_up_sync(0xffffffffu, x, off);
        if (lane >= off) x += y;
    }
    __shared__ int ws[8];
    if (lane == 31) ws[wp] = x;
    __syncthreads();
    if (t == 0){
        int run = 0;
        #pragma unroll
        for (int i = 0; i < 8; i++){ int tmp = ws[i]; ws[i] = run; run += tmp; }
        g_bsum[b] = run;
    }
    __syncthreads();
    if (n < NN) g_rowptr[n] = x - v + ws[wp];
}

__global__ void k_scan2(){
    int t = threadIdx.x;
    int v = (t < SCAN_NB) ? g_bsum[t] : 0;
    int lane = t & 31, wp = t >> 5;
    int x = v;
    #pragma unroll
    for (int off = 1; off < 32; off <<= 1){
        int y = __shfl_up_sync(0xffffffffu, x, off);
        if (lane >= off) x += y;
    }
    __shared__ int ws[8];
    if (lane == 31) ws[wp] = x;
    __syncthreads();
    if (t == 0){
        int run = 0;
        #pragma unroll
        for (int i = 0; i < 8; i++){ int tmp = ws[i]; ws[i] = run; run += tmp; }
        g_rowptr[NN] = run;
    }
    __syncthreads();
    if (t < SCAN_NB) g_bsum[t] = x - v + ws[wp];
}

__global__ void k_scan3(){
    int n = blockIdx.x*256 + threadIdx.x;
    if (n < NN) g_rowptr[n] += g_bsum[n >> 8];
}

__global__ void k_scatter(const int* __restrict__ ei, const float* __restrict__ ea){
    int e = blockIdx.x*blockDim.x + threadIdx.x;
    if (e >= NE) return;
    int s = ei[e];
    int d = ei[NE + e];
    int p = g_rowptr[d] + atomicAdd(&g_fill[d], 1);
    g_srcs[p] = s;
    const float* a = ea + e*3;
    g_ea[p] = make_float4(a[0], a[1], a[2], 0.f);
}

// initial segment sums; the ONLY writer of g_gcnt / g_bccnt (constant after)
__global__ void k_seginit(const int* __restrict__ batch, const float* __restrict__ xm){
    const int nchunk = (NN + gridDim.x - 1) / gridDim.x;
    int n0 = blockIdx.x * nchunk;
    int n1 = min(n0 + nchunk, NN);
    int t = threadIdx.x;
    if (n0 >= n1) return;
    int cur = batch[n0];
    float aG = 0.f, aB = 0.f, cG = 0.f, cB = 0.f;
    for (int n = n0; n < n1; n++){
        int b = batch[n];
        if (b != cur){
            atomicAdd(&g_gsum[cur*HD+t], aG);
            atomicAdd(&g_bcsum[cur*HD+t], aB);
            if (t == 0){ atomicAdd(&g_gcnt[cur], cG); atomicAdd(&g_bccnt[cur], cB); }
            aG = aB = cG = cB = 0.f; cur = b;
        }
        float hv = g_h[n*HD + t];
        float bc = xm[n*3 + 2];
        aG += hv; aB += hv*bc;
        if (t == 0){ cG += 1.f; cB += bc; }
    }
    atomicAdd(&g_gsum[cur*HD+t], aG);
    atomicAdd(&g_bcsum[cur*HD+t], aB);
    if (t == 0){ atomicAdd(&g_gcnt[cur], cG); atomicAdd(&g_bccnt[cur], cB); }
}

// gbc = b_upd + xBC @ Wu[384:512]   (constant over repeats)
__global__ void k_initgbc(const float* __restrict__ Wu, const float* __restrict__ bu){
    int g = blockIdx.x, t = threadIdx.x;
    __shared__ float sx[128];
    float bcc = fmaxf(g_bccnt[g], 1.f);
    sx[t] = g_bcsum[g*HD + t] / bcc;
    __syncthreads();
    float acc = bu[t];
    #pragma unroll 4
    for (int k = 0; k < 128; k++) acc += sx[k] * Wu[(384+k)*128 + t];
    g_gbc[g*HD + t] = acc;
}

// gb = gbc + xg @ Wu[256:384]; finishes seg-mean; re-zeros SUMS only.
__global__ void k_prep(const float* __restrict__ Wu){
    int g = blockIdx.x, t = threadIdx.x;
    __shared__ float sx[128];
    float c = fmaxf(g_gcnt[g], 1.f);
    sx[t] = g_gsum[g*HD + t] / c;
    __syncthreads();
    float acc = g_gbc[g*HD + t];
    #pragma unroll 4
    for (int k = 0; k < 128; k++) acc += sx[k] * Wu[(256+k)*128 + t];
    g_gb[g*HD + t] = acc;
    g_gsum[g*HD + t] = 0.f;
}

// seg sums only (counts are constant, owned by k_seginit)
__global__ void k_segsum(const int* __restrict__ batch){
    const int nchunk = (NN + gridDim.x - 1) / gridDim.x;
    int n0 = blockIdx.x * nchunk;
    int n1 = min(n0 + nchunk, NN);
    int t = threadIdx.x;
    if (n0 >= n1) return;
    int cur = batch[n0];
    float aG = 0.f;
    for (int n = n0; n < n1; n++){
        int b = batch[n];
        if (b != cur){
            atomicAdd(&g_gsum[cur*HD+t], aG);
            aG = 0.f; cur = b;
        }
        aG += g_h[n*HD + t];
    }
    atomicAdd(&g_gsum[cur*HD+t], aG);
}

// ---- GEMM1: Psrc(fp16)/Pdst(fp32) = h @ B1^T  (single-pass, 3 CTAs/SM) ------
__global__ void __launch_bounds__(256, 3) k_gemm1(const float* __restrict__ bm){
    extern __shared__ __half sm[];
    uint32_t sb = (uint32_t)__cvta_generic_to_shared(sm);
    int tid = threadIdx.x;
    int w = tid >> 5, l = tid & 31;
    int row0 = blockIdx.x * 128;
    int cchunk = blockIdx.y;          // 0 -> Psrc (fp16), 1 -> Pdst (fp32, +b_msg)

    load_A_hi(g_h + (size_t)row0*128, sm, tid);
    load_B_tile(g_B1h + (size_t)cchunk*128*128, 128, sm + SM_B1, tid);
    __syncthreads();

    float acc[2][8][4];
    #pragma unroll
    for (int mb = 0; mb < 2; mb++)
        #pragma unroll
        for (int nb = 0; nb < 8; nb++)
            #pragma unroll
            for (int c = 0; c < 4; c++) acc[mb][nb][c] = 0.f;

    mma_stage1(sb, acc, w, l);

    int wm = w >> 1, wn = w & 1;
    int g = l >> 2, t2 = (l & 3) * 2;
    if (cchunk == 0){
        #pragma unroll
        for (int mb = 0; mb < 2; mb++){
            int row = row0 + wm*32 + mb*16 + g;
            #pragma unroll
            for (int nb = 0; nb < 8; nb++){
                int col = wn*64 + nb*8 + t2;
                *(__half2*)&g_Psrc[(size_t)row*128 + col] =
                    __floats2half2_rn(acc[mb][nb][0], acc[mb][nb][1]);
                *(__half2*)&g_Psrc[(size_t)(row+8)*128 + col] =
                    __floats2half2_rn(acc[mb][nb][2], acc[mb][nb][3]);
            }
        }
    } else {
        #pragma unroll
        for (int mb = 0; mb < 2; mb++){
            int row = row0 + wm*32 + mb*16 + g;
            #pragma unroll
            for (int nb = 0; nb < 8; nb++){
                int col = wn*64 + nb*8 + t2;
                float bias0 = bm[col], bias1 = bm[col+1];
                *(float2*)&g_Pdst[(size_t)row*128 + col] =
                    make_float2(acc[mb][nb][0] + bias0, acc[mb][nb][1] + bias1);
                *(float2*)&g_Pdst[(size_t)(row+8)*128 + col] =
                    make_float2(acc[mb][nb][2] + bias0, acc[mb][nb][3] + bias1);
            }
        }
    }
}

// ------- edge aggregation over CSR: one warp per node, 4 channels/lane --------
__global__ void k_agg(const float* __restrict__ Wm){
    int n = blockIdx.x*8 + (threadIdx.x >> 5);
    if (n >= NN) return;
    int l = threadIdx.x & 31;
    int c = l*4;
    float4 base = *(const float4*)&g_Pdst[(size_t)n*128 + c];   // includes b_msg
    float4 w0 = *(const float4*)&Wm[256*128 + c];
    float4 w1 = *(const float4*)&Wm[257*128 + c];
    float4 w2 = *(const float4*)&Wm[258*128 + c];
    int s0 = g_rowptr[n], s1 = g_rowptr[n+1];
    float a0 = 0.f, a1 = 0.f, a2 = 0.f, a3 = 0.f;
    int k = s0;
    for (; k + 1 < s1; k += 2){
        int sA = g_srcs[k], sB = g_srcs[k+1];
        float4 eA = g_ea[k], eB = g_ea[k+1];
        uint2 pA = *(const uint2*)&g_Psrc[(size_t)sA*128 + c];
        uint2 pB = *(const uint2*)&g_Psrc[(size_t)sB*128 + c];
        float2 pA01 = __half22float2(*(__half2*)&pA.x);
        float2 pA23 = __half22float2(*(__half2*)&pA.y);
        float2 pB01 = __half22float2(*(__half2*)&pB.x);
        float2 pB23 = __half22float2(*(__half2*)&pB.y);
        float tA0 = base.x + eA.x*w0.x + eA.y*w1.x + eA.z*w2.x;
        float tA1 = base.y + eA.x*w0.y + eA.y*w1.y + eA.z*w2.y;
        float tA2 = base.z + eA.x*w0.z + eA.y*w1.z + eA.z*w2.z;
        float tA3 = base.w + eA.x*w0.w + eA.y*w1.w + eA.z*w2.w;
        float tB0 = base.x + eB.x*w0.x + eB.y*w1.x + eB.z*w2.x;
        float tB1 = base.y + eB.x*w0.y + eB.y*w1.y + eB.z*w2.y;
        float tB2 = base.z + eB.x*w0.z + eB.y*w1.z + eB.z*w2.z;
        float tB3 = base.w + eB.x*w0.w + eB.y*w1.w + eB.z*w2.w;
        a0 += fmaxf(pA01.x + tA0, 0.f) + fmaxf(pB01.x + tB0, 0.f);
        a1 += fmaxf(pA01.y + tA1, 0.f) + fmaxf(pB01.y + tB1, 0.f);
        a2 += fmaxf(pA23.x + tA2, 0.f) + fmaxf(pB23.x + tB2, 0.f);
        a3 += fmaxf(pA23.y + tA3, 0.f) + fmaxf(pB23.y + tB3, 0.f);
    }
    if (k < s1){
        int s = g_srcs[k];
        float4 e = g_ea[k];
        uint2 p = *(const uint2*)&g_Psrc[(size_t)s*128 + c];
        float2 p01 = __half22float2(*(__half2*)&p.x);
        float2 p23 = __half22float2(*(__half2*)&p.y);
        a0 += fmaxf(p01.x + base.x + e.x*w0.x + e.y*w1.x + e.z*w2.x, 0.f);
        a1 += fmaxf(p01.y + base.y + e.x*w0.y + e.y*w1.y + e.z*w2.y, 0.f);
        a2 += fmaxf(p23.x + base.z + e.x*w0.z + e.y*w1.z + e.z*w2.z, 0.f);
        a3 += fmaxf(p23.y + base.w + e.x*w0.w + e.y*w1.w + e.z*w2.w, 0.f);
    }
    float inv = g_invdeg[n];
    *(float4*)&g_agg[(size_t)n*HD + c] = make_float4(a0*inv, a1*inv, a2*inv, a3*inv);
}

// ---------------- GEMM2: h += relu([h|agg] @ B2^T + gb[batch]) (dual-pass) ----
__global__ void __launch_bounds__(256, 2) k_gemm2(const int* __restrict__ batch){
    extern __shared__ __half sm[];
    uint32_t sb = (uint32_t)__cvta_generic_to_shared(sm);
    int tid = threadIdx.x;
    int w = tid >> 5, l = tid & 31;
    int row0 = blockIdx.x * 128;

    float acc[2][8][4];
    #pragma unroll
    for (int mb = 0; mb < 2; mb++)
        #pragma unroll
        for (int nb = 0; nb < 8; nb++)
            #pragma unroll
            for (int c = 0; c < 4; c++) acc[mb][nb][c] = 0.f;

    for (int kh = 0; kh < 2; kh++){
        if (kh) __syncthreads();
        const float* A = (kh == 0 ? g_h : g_agg) + (size_t)row0*128;
        load_A_tile(A, sm + SM_AHI, sm + SM_ALO, tid);
        load_B_tile(g_B2h + kh*128, 256, sm + SM_B2, tid);
        __syncthreads();
        mma_stage2(sb, acc, w, l);
    }

    int wm = w >> 1, wn = w & 1;
    int g = l >> 2, t2 = (l & 3) * 2;
    #pragma unroll
    for (int mb = 0; mb < 2; mb++){
        int row_a = row0 + wm*32 + mb*16 + g;
        #pragma unroll
        for (int half = 0; half < 2; half++){
            int row = row_a + half*8;
            if (row < NN){
                int b = batch[row];
                #pragma unroll
                for (int nb = 0; nb < 8; nb++){
                    int col = wn*64 + nb*8 + t2;
                    float v0 = acc[mb][nb][half*2+0] + g_gb[b*128 + col];
                    float v1 = acc[mb][nb][half*2+1] + g_gb[b*128 + col + 1];
                    float* hp = g_h + (size_t)row*128 + col;
                    float2 hv = *(float2*)hp;
                    hv.x += fmaxf(v0, 0.f);
                    hv.y += fmaxf(v1, 0.f);
                    *(float2*)hp = hv;
                }
            } else {
                #pragma unroll
                for (int nb = 0; nb < 8; nb++){
                    int col = wn*64 + nb*8 + t2;
                    *(float2*)&g_h[(size_t)row*128 + col] = make_float2(0.f, 0.f);
                }
            }
        }
    }
}

// ---------------- decode + weighted global sums (warp per 32 nodes) ----------
__global__ void k_decode(const float* __restrict__ Wd, const float* __restrict__ bd,
                         float* __restrict__ out){
    int gw = (blockIdx.x*blockDim.x + threadIdx.x) >> 5;
    int l = threadIdx.x & 31;
    int n0 = gw * 32;
    if (n0 >= NN) return;
    int n1 = min(n0 + 32, NN);
    float wd0[4], wd1[4], wd2[4], wd3[4];
    #pragma unroll
    for (int c = 0; c < 4; c++){
        wd0[c] = Wd[(l*4+0)*4 + c];
        wd1[c] = Wd[(l*4+1)*4 + c];
        wd2[c] = Wd[(l*4+2)*4 + c];
        wd3[c] = Wd[(l*4+3)*4 + c];
    }
    float b0 = bd[0], b1 = bd[1], b2 = bd[2], b3 = bd[3];
    float S0=0.f, S1=0.f, S2=0.f, S3=0.f, wacc=0.f;
    for (int n = n0; n < n1; n++){
        float4 hv = *(const float4*)&g_h[(size_t)n*128 + l*4];
        float wn = g_w[n];
        float onew = 1.f + wn;
        S0 += onew*hv.x; S1 += onew*hv.y; S2 += onew*hv.z; S3 += onew*hv.w;
        if (l == 0) wacc += wn;
        float p0 = hv.x*wd0[0] + hv.y*wd1[0] + hv.z*wd2[0] + hv.w*wd3[0];
        float p1 = hv.x*wd0[1] + hv.y*wd1[1] + hv.z*wd2[1] + hv.w*wd3[1];
        float p2 = hv.x*wd0[2] + hv.y*wd1[2] + hv.z*wd2[2] + hv.w*wd3[2];
        float p3 = hv.x*wd0[3] + hv.y*wd1[3] + hv.z*wd2[3] + hv.w*wd3[3];
        #pragma unroll
        for (int off = 16; off > 0; off >>= 1){
            p0 += __shfl_down_sync(0xffffffffu, p0, off);
            p1 += __shfl_down_sync(0xffffffffu, p1, off);
            p2 += __shfl_down_sync(0xffffffffu, p2, off);
            p3 += __shfl_down_sync(0xffffffffu, p3, off);
        }
        if (l == 0)
            *(float4*)&out[(size_t)(1+n)*4] = make_float4(p0+b0, p1+b1, p2+b2, p3+b3);
    }
    atomicAdd(&g_S[l*4+0], S0);
    atomicAdd(&g_S[l*4+1], S1);
    atomicAdd(&g_S[l*4+2], S2);
    atomicAdd(&g_S[l*4+3], S3);
    if (l == 0) atomicAdd(&g_sw, wacc);
}

__global__ void k_final(const float* __restrict__ Wd, const float* __restrict__ bd,
                        float* __restrict__ out){
    __shared__ float sred[4][4];
    int t = threadIdx.x;
    int lane = t & 31, wp = t >> 5;
    float enc = g_S[t] / ((float)NN + g_sw);
    float p0 = enc*Wd[t*4], p1 = enc*Wd[t*4+1], p2 = enc*Wd[t*4+2], p3 = enc*Wd[t*4+3];
    #pragma unroll
    for (int off = 16; off > 0; off >>= 1){
        p0 += __shfl_down_sync(0xffffffffu, p0, off);
        p1 += __shfl_down_sync(0xffffffffu, p1, off);
        p2 += __shfl_down_sync(0xffffffffu, p2, off);
        p3 += __shfl_down_sync(0xffffffffu, p3, off);
    }
    if (lane == 0){ sred[wp][0]=p0; sred[wp][1]=p1; sred[wp][2]=p2; sred[wp][3]=p3; }
    __syncthreads();
    if (t < 4)
        out[t] = sred[0][t] + sred[1][t] + sred[2][t] + sred[3][t] + bd[t];
}

// ---------------- launch ----------------
extern "C" void kernel_launch(void* const* d_in, const int* in_sizes, int n_in,
                              void* d_out, int out_size){
    (void)in_sizes; (void)n_in; (void)out_size;
    const float* x   = (const float*)d_in[0];
    const float* xm  = (const float*)d_in[1];
    const int*   ei  = (const int*)  d_in[2];
    const float* ea  = (const float*)d_in[3];
    const float* pos = (const float*)d_in[4];
    const int*   bat = (const int*)  d_in[5];
    const float* sp  = (const float*)d_in[6];
    const float* M   = (const float*)d_in[7];
    const float* We  = (const float*)d_in[8];
    const float* be  = (const float*)d_in[9];
    const float* Wm  = (const float*)d_in[10];
    const float* bm  = (const float*)d_in[11];
    const float* Wu  = (const float*)d_in[12];
    const float* bu  = (const float*)d_in[13];
    const float* Wd  = (const float*)d_in[14];
    const float* bd  = (const float*)d_in[15];
    float* out = (float*)d_out;

    static int attr_done = 0;
    if (!attr_done){
        cudaFuncSetAttribute(k_gemm1, cudaFuncAttributeMaxDynamicSharedMemorySize, SM1_TOTAL_BYTES);
        cudaFuncSetAttribute(k_gemm2, cudaFuncAttributeMaxDynamicSharedMemorySize, SM2_TOTAL_BYTES);
        attr_done = 1;
    }

    dim3 g1(NBLK, 2);

    k_setup  <<<(NN+255)/256, 256>>>(Wm, Wu);
    k_encode <<<(NN+7)/8, 256>>>(x, xm, We, be);
    k_wcoef  <<<(NN+255)/256, 256>>>(pos, M, sp);
    k_count  <<<(NE+255)/256, 256>>>(ei);
    k_scan1  <<<SCAN_NB, 256>>>();
    k_gemm1  <<<g1, 256, SM1_TOTAL_BYTES>>>(bm);   // repeat 0 GEMM1 (hoisted)
    k_scan2  <<<1, 256>>>();
    k_scan3  <<<SCAN_NB, 256>>>();
    k_scatter<<<(NE+255)/256, 256>>>(ei, ea);
    k_seginit<<<784, 128>>>(bat, xm);
    k_initgbc<<<NBATCH, 128>>>(Wu, bu);
    k_prep   <<<NBATCH, 128>>>(Wu);

    for (int r = 0; r < 4; r++){
        if (r > 0) k_gemm1<<<g1, 256, SM1_TOTAL_BYTES>>>(bm);
        k_agg  <<<(NN+7)/8, 256>>>(Wm);
        k_gemm2<<<NBLK, 256, SM2_TOTAL_BYTES>>>(bat);
        if (r < 3){
            k_segsum<<<784, 128>>>(bat);
            k_prep  <<<NBATCH, 128>>>(Wu);
        }
    }

    k_decode<<<196, 256>>>(Wd, bd, out);
    k_final <<<1, 128>>>(Wd, bd, out);
}